// round 7
// baseline (speedup 1.0000x reference)
#include <cuda_runtime.h>

// Problem constants
#define BB   512
#define TT   65536
#define CL   128                  // chunk length
#define NC   (TT / CL)            // 512 chunks per row
#define NTH  256
#define NRP  (BB / 2)             // 256 row pairs
#define GRID (NRP * 2)            // 512 blocks (h-split: 256 chunks per block)

#define BUF_F4   (NTH * 9)
#define SMEM_STG (2 * BUF_F4 * 16)    // 73728 bytes: two padded float4 buffers

typedef unsigned long long u64f;

// Scratch: only the transposed packed intermediate remains.
__device__ __align__(16) u64f g_y1t[(size_t)NRP * TT];   // y1 transposed packed (128 MB)
__device__ float g_coef[17];    // [0..8]=b/a0, [9..16]=-(a[1..8]/a0)

// ---------------------------------------------------------------------------
#define FFMA2(d, a, b, c) asm("fma.rn.f32x2 %0, %1, %2, %3;" : "=l"(d) : "l"(a), "l"(b), "l"(c))

__device__ __forceinline__ u64f pk2(float lo, float hi) {
    u64f r; asm("mov.b64 %0, {%1, %2};" : "=l"(r) : "f"(lo), "f"(hi)); return r;
}
__device__ __forceinline__ float2 upk(u64f v) {
    float2 r; asm("mov.b64 {%0, %1}, %2;" : "=f"(r.x), "=f"(r.y) : "l"(v)); return r;
}

__device__ __forceinline__ u64f pstep(u64f x, u64f* z, const u64f* cb, const u64f* cna) {
    u64f y, t;
    FFMA2(y, cb[0], x, z[0]);
    #pragma unroll
    for (int i = 0; i < 7; i++) {
        FFMA2(t, cb[i + 1], x, z[i + 1]);
        FFMA2(z[i], cna[i], y, t);
    }
    u64f zz = 0ULL;
    FFMA2(t, cb[8], x, zz);
    FFMA2(z[7], cna[7], y, t);
    return y;
}

#define LOAD_COEF_PK()                                         \
    u64f cb[9], cna[8];                                        \
    _Pragma("unroll")                                          \
    for (int i_ = 0; i_ < 9; i_++) { float c_ = g_coef[i_];    \
        cb[i_] = pk2(c_, c_); }                                \
    _Pragma("unroll")                                          \
    for (int i_ = 0; i_ < 8; i_++) { float c_ = g_coef[9 + i_];\
        cna[i_] = pk2(c_, c_); }

// ---------------------------------------------------------------------------
// Setup: normalize coefficients only (no transition matrices needed anymore).
// ---------------------------------------------------------------------------
__global__ void setup_kernel(const float* __restrict__ b, const float* __restrict__ a) {
    if (threadIdx.x == 0) {
        float inv = 1.0f / a[0];
        #pragma unroll
        for (int i = 0; i < 9; i++) {
            g_coef[i] = b[i] * inv;
            if (i >= 1) g_coef[8 + i] = -(a[i] * inv);
        }
    }
}

// ---------------------------------------------------------------------------
// K1: forward filtfilt half. Thread for chunk c zero-state filters chunks
// c-2, c-1 (warm-up; ||A^256|| ~ 1e-9 truncation), then chunk c, writing y1T
// inline (coalesced STG.64). x staged through smem per 32-sample stage.
// ---------------------------------------------------------------------------
__global__ void __launch_bounds__(NTH, 3) fwd_k(const float* __restrict__ x,
                                                u64f* __restrict__ y1t) {
    extern __shared__ char smc[];
    float4* b0 = (float4*)smc;
    float4* b1 = b0 + BUF_F4;

    int rp = blockIdx.x >> 1, h = blockIdx.x & 1, t = threadIdx.x;
    int c = h * 256 + t;
    const float* p0 = x + (size_t)(rp * 2) * TT;
    const float* p1 = p0 + TT;
    u64f* yt = g_y1t + (size_t)rp * TT;
    (void)y1t;

    LOAD_COEF_PK();
    u64f z[8];
    #pragma unroll
    for (int i2 = 0; i2 < 8; i2++) z[i2] = 0ULL;

    #pragma unroll 1
    for (int k = 0; k < 3; k++) {
        #pragma unroll 1
        for (int s = 0; s < 4; s++) {
            // cooperative coalesced stage load: slot tt holds chunk h*256+tt-2+k
            #pragma unroll
            for (int l = 0; l < 8; l++) {
                int q = l * NTH + t;
                int tt = q >> 3, j = q & 7;
                int ac = h * 256 + tt - 2 + k;
                float4 va = make_float4(0.f, 0.f, 0.f, 0.f);
                float4 vb = va;
                if (ac >= 0) {
                    int base = ac * CL + s * 32 + 4 * j;
                    va = *reinterpret_cast<const float4*>(p0 + base);
                    vb = *reinterpret_cast<const float4*>(p1 + base);
                }
                b0[tt * 9 + j] = va;
                b1[tt * 9 + j] = vb;
            }
            __syncthreads();
            if (k < 2) {
                // warm-up: advance state, discard outputs
                #pragma unroll
                for (int j2 = 0; j2 < 8; j2++) {
                    float4 a4 = b0[t * 9 + j2];
                    float4 c4 = b1[t * 9 + j2];
                    pstep(pk2(a4.x, c4.x), z, cb, cna);
                    pstep(pk2(a4.y, c4.y), z, cb, cna);
                    pstep(pk2(a4.z, c4.z), z, cb, cna);
                    pstep(pk2(a4.w, c4.w), z, cb, cna);
                }
            } else {
                // own chunk: emit y to transposed layout inline
                #pragma unroll
                for (int j2 = 0; j2 < 8; j2++) {
                    float4 a4 = b0[t * 9 + j2];
                    float4 c4 = b1[t * 9 + j2];
                    u64f yp0 = pstep(pk2(a4.x, c4.x), z, cb, cna);
                    u64f yp1 = pstep(pk2(a4.y, c4.y), z, cb, cna);
                    u64f yp2 = pstep(pk2(a4.z, c4.z), z, cb, cna);
                    u64f yp3 = pstep(pk2(a4.w, c4.w), z, cb, cna);
                    int ibase = s * 32 + 4 * j2;
                    yt[(size_t)(ibase + 0) * NC + c] = yp0;
                    yt[(size_t)(ibase + 1) * NC + c] = yp1;
                    yt[(size_t)(ibase + 2) * NC + c] = yp2;
                    yt[(size_t)(ibase + 3) * NC + c] = yp3;
                }
            }
            __syncthreads();
        }
    }
}

// ---------------------------------------------------------------------------
// K2: backward filtfilt half over y1T. Thread for backward chunk cbk filters
// original chunks c+2, c+1 (warm-up, direct coalesced LDG.64 from y1T, zero
// staging), then chunk c, staging output to physical layout.
// ---------------------------------------------------------------------------
__global__ void __launch_bounds__(NTH, 3) bwd_k(float* __restrict__ out) {
    extern __shared__ char smc[];
    float4* b0 = (float4*)smc;
    float4* b1 = b0 + BUF_F4;

    int rp = blockIdx.x >> 1, h = blockIdx.x & 1, t = threadIdx.x;
    int cbk = h * 256 + t;          // backward chunk index
    int c   = NC - 1 - cbk;         // original chunk index
    const u64f* yt = g_y1t + (size_t)rp * TT;
    float* o0 = out + (size_t)(rp * 2) * TT;
    float* o1 = o0 + TT;

    LOAD_COEF_PK();
    u64f z[8];
    #pragma unroll
    for (int i2 = 0; i2 < 8; i2++) z[i2] = 0ULL;

    // ---- warm-up: original chunks c+2, c+1, descending sample order ----
    #pragma unroll 1
    for (int k = 0; k < 2; k++) {
        int ab = cbk - 2 + k;           // backward chunk being traversed
        int cc = c + 2 - k;             // original chunk index
        bool valid = (ab >= 0);
        #pragma unroll 1
        for (int s = 0; s < 4; s++) {
            #pragma unroll
            for (int jj = 0; jj < 8; jj++) {
                int i3 = 127 - s * 32 - 4 * jj;
                u64f x3 = valid ? yt[(size_t)(i3 - 0) * NC + cc] : 0ULL;
                u64f x2 = valid ? yt[(size_t)(i3 - 1) * NC + cc] : 0ULL;
                u64f x1 = valid ? yt[(size_t)(i3 - 2) * NC + cc] : 0ULL;
                u64f x0 = valid ? yt[(size_t)(i3 - 3) * NC + cc] : 0ULL;
                pstep(x3, z, cb, cna);
                pstep(x2, z, cb, cna);
                pstep(x1, z, cb, cna);
                pstep(x0, z, cb, cna);
            }
        }
    }

    // ---- own chunk c: produce outputs, stage to physical layout ----
    #pragma unroll 1
    for (int s = 0; s < 4; s++) {
        #pragma unroll
        for (int jj = 0; jj < 8; jj++) {
            int i3 = 127 - s * 32 - 4 * jj;
            u64f x3 = yt[(size_t)(i3 - 0) * NC + c];
            u64f x2 = yt[(size_t)(i3 - 1) * NC + c];
            u64f x1 = yt[(size_t)(i3 - 2) * NC + c];
            u64f x0 = yt[(size_t)(i3 - 3) * NC + c];
            float2 y3 = upk(pstep(x3, z, cb, cna));   // sample i3
            float2 y2 = upk(pstep(x2, z, cb, cna));   // i3-1
            float2 y1v = upk(pstep(x1, z, cb, cna));  // i3-2
            float2 y0 = upk(pstep(x0, z, cb, cna));   // i3-3
            int jl = 7 - jj;
            b0[t * 9 + jl] = make_float4(y0.x, y1v.x, y2.x, y3.x);
            b1[t * 9 + jl] = make_float4(y0.y, y1v.y, y2.y, y3.y);
        }
        __syncthreads();
        #pragma unroll
        for (int l = 0; l < 8; l++) {
            int q = l * NTH + t;
            int tt = q >> 3, j = q & 7;
            int cc2 = NC - 1 - (h * 256 + tt);
            int base = cc2 * CL + (96 - 32 * s) + 4 * j;
            *reinterpret_cast<float4*>(o0 + base) = b0[tt * 9 + j];
            *reinterpret_cast<float4*>(o1 + base) = b1[tt * 9 + j];
        }
        __syncthreads();
    }
}

extern "C" void kernel_launch(void* const* d_in, const int* in_sizes, int n_in,
                              void* d_out, int out_size) {
    const float* x = (const float*)d_in[0];
    const float* b = (const float*)d_in[1];
    const float* a = (const float*)d_in[2];
    float* out = (float*)d_out;

    u64f* pyt = nullptr;
    cudaGetSymbolAddress((void**)&pyt, g_y1t);

    static bool attr_done = false;
    if (!attr_done) {
        cudaFuncSetAttribute(fwd_k, cudaFuncAttributeMaxDynamicSharedMemorySize, SMEM_STG);
        cudaFuncSetAttribute(bwd_k, cudaFuncAttributeMaxDynamicSharedMemorySize, SMEM_STG);
        attr_done = true;
    }

    setup_kernel<<<1, 32>>>(b, a);
    fwd_k<<<GRID, NTH, SMEM_STG>>>(x, pyt);
    bwd_k<<<GRID, NTH, SMEM_STG>>>(out);
}

// round 8
// speedup vs baseline: 1.3283x; 1.3283x over previous
#include <cuda_runtime.h>

// Problem constants
#define BB   512
#define TT   65536
#define CL   256                  // chunk length (samples per thread)
#define NC   (TT / CL)            // 256 chunks per row
#define WUS  6                    // warm-up stages (6*32 = 192 samples)
#define NTH  128                  // threads per block = half a row pair's chunks
#define NRP  (BB / 2)             // 256 row pairs
#define GRID (NRP * 2)            // 512 blocks

#define BUF_F4   (NTH * 9)
#define SMEM_STG (2 * BUF_F4 * 16)    // 36864 bytes

typedef unsigned long long u64f;

// Intermediate: y1 transposed-packed: yt[iw * NC + c], iw = index within chunk,
// c = chunk index; value packs the two rows of the pair (lo=row0, hi=row1).
__device__ __align__(16) u64f g_y1t[(size_t)NRP * TT];   // 128 MB
__device__ float g_coef[17];    // [0..8]=b/a0, [9..16]=-(a[1..8]/a0)

// ---------------------------------------------------------------------------
#define FFMA2(d, a, b, c) asm("fma.rn.f32x2 %0, %1, %2, %3;" : "=l"(d) : "l"(a), "l"(b), "l"(c))

__device__ __forceinline__ u64f pk2(float lo, float hi) {
    u64f r; asm("mov.b64 %0, {%1, %2};" : "=l"(r) : "f"(lo), "f"(hi)); return r;
}
__device__ __forceinline__ float2 upk(u64f v) {
    float2 r; asm("mov.b64 {%0, %1}, %2;" : "=f"(r.x), "=f"(r.y) : "l"(v)); return r;
}

__device__ __forceinline__ u64f pstep(u64f x, u64f* z, const u64f* cb, const u64f* cna) {
    u64f y, t;
    FFMA2(y, cb[0], x, z[0]);
    #pragma unroll
    for (int i = 0; i < 7; i++) {
        FFMA2(t, cb[i + 1], x, z[i + 1]);
        FFMA2(z[i], cna[i], y, t);
    }
    u64f zz = 0ULL;
    FFMA2(t, cb[8], x, zz);
    FFMA2(z[7], cna[7], y, t);
    return y;
}

#define LOAD_COEF_PK()                                         \
    u64f cb[9], cna[8];                                        \
    _Pragma("unroll")                                          \
    for (int i_ = 0; i_ < 9; i_++) { float c_ = g_coef[i_];    \
        cb[i_] = pk2(c_, c_); }                                \
    _Pragma("unroll")                                          \
    for (int i_ = 0; i_ < 8; i_++) { float c_ = g_coef[9 + i_];\
        cna[i_] = pk2(c_, c_); }

// ---------------------------------------------------------------------------
__global__ void setup_kernel(const float* __restrict__ b, const float* __restrict__ a) {
    if (threadIdx.x == 0) {
        float inv = 1.0f / a[0];
        #pragma unroll
        for (int i = 0; i < 9; i++) {
            g_coef[i] = b[i] * inv;
            if (i >= 1) g_coef[8 + i] = -(a[i] * inv);
        }
    }
}

// ---------------------------------------------------------------------------
// fwd: thread owns chunk c. Zero-state warm-up over the 192 preceding samples
// (truncation ~2e-7), then filters its 256-sample chunk, writing y1T inline
// (coalesced STG.64). x staged per 32-sample stage through smem.
// ---------------------------------------------------------------------------
__global__ void __launch_bounds__(NTH) fwd_k(const float* __restrict__ x) {
    extern __shared__ char smc[];
    float4* b0 = (float4*)smc;
    float4* b1 = b0 + BUF_F4;

    int rp = blockIdx.x >> 1, h = blockIdx.x & 1, t = threadIdx.x;
    int c = h * NTH + t;                 // chunk 0..255
    const float* p0 = x + (size_t)(rp * 2) * TT;
    const float* p1 = p0 + TT;
    u64f* yt = g_y1t + (size_t)rp * TT;

    LOAD_COEF_PK();
    u64f z[8];
    #pragma unroll
    for (int i2 = 0; i2 < 8; i2++) z[i2] = 0ULL;

    #pragma unroll 1
    for (int k = 0; k < 8 + WUS; k++) {
        // slot tt holds 32-sample stage (h*NTH+tt)*8 + k - WUS of this row
        #pragma unroll
        for (int l = 0; l < 8; l++) {
            int q = l * NTH + t;
            int tt = q >> 3, j = q & 7;
            int sg = (h * NTH + tt) * 8 + (k - WUS);
            float4 va = make_float4(0.f, 0.f, 0.f, 0.f);
            float4 vb = va;
            if (sg >= 0) {
                int base = sg * 32 + 4 * j;
                va = *reinterpret_cast<const float4*>(p0 + base);
                vb = *reinterpret_cast<const float4*>(p1 + base);
            }
            b0[tt * 9 + j] = va;
            b1[tt * 9 + j] = vb;
        }
        __syncthreads();
        if (k < WUS) {
            #pragma unroll
            for (int j2 = 0; j2 < 8; j2++) {
                float4 a4 = b0[t * 9 + j2];
                float4 c4 = b1[t * 9 + j2];
                pstep(pk2(a4.x, c4.x), z, cb, cna);
                pstep(pk2(a4.y, c4.y), z, cb, cna);
                pstep(pk2(a4.z, c4.z), z, cb, cna);
                pstep(pk2(a4.w, c4.w), z, cb, cna);
            }
        } else {
            #pragma unroll
            for (int j2 = 0; j2 < 8; j2++) {
                float4 a4 = b0[t * 9 + j2];
                float4 c4 = b1[t * 9 + j2];
                u64f yp0 = pstep(pk2(a4.x, c4.x), z, cb, cna);
                u64f yp1 = pstep(pk2(a4.y, c4.y), z, cb, cna);
                u64f yp2 = pstep(pk2(a4.z, c4.z), z, cb, cna);
                u64f yp3 = pstep(pk2(a4.w, c4.w), z, cb, cna);
                int iw = (k - WUS) * 32 + 4 * j2;    // within-chunk index
                yt[(size_t)(iw + 0) * NC + c] = yp0;
                yt[(size_t)(iw + 1) * NC + c] = yp1;
                yt[(size_t)(iw + 2) * NC + c] = yp2;
                yt[(size_t)(iw + 3) * NC + c] = yp3;
            }
        }
        __syncthreads();
    }
}

// ---------------------------------------------------------------------------
// bwd: thread owns original chunk c; runs the time-reversed filter. Warm-up
// over the 192 samples AFTER the chunk (in chunk c+1; zeros past the end,
// which exactly matches the zero initial state). Direct coalesced LDG.64 from
// y1T, no input staging; output staged to physical layout.
// ---------------------------------------------------------------------------
__global__ void __launch_bounds__(NTH) bwd_k(float* __restrict__ out) {
    extern __shared__ char smc[];
    float4* b0 = (float4*)smc;
    float4* b1 = b0 + BUF_F4;

    int rp = blockIdx.x >> 1, h = blockIdx.x & 1, t = threadIdx.x;
    int c = h * NTH + t;                 // original chunk
    const u64f* yt = g_y1t + (size_t)rp * TT;
    float* o0 = out + (size_t)(rp * 2) * TT;
    float* o1 = o0 + TT;

    LOAD_COEF_PK();
    u64f z[8];
    #pragma unroll
    for (int i2 = 0; i2 < 8; i2++) z[i2] = 0ULL;

    // ---- warm-up: samples of chunk c+1 with iw = 191 down to 0 ----
    {
        bool valid = (c + 1 < NC);
        int cn = valid ? (c + 1) : c;    // safe address; value zeroed when !valid
        #pragma unroll 1
        for (int s = 0; s < WUS; s++) {
            #pragma unroll
            for (int g4 = 0; g4 < 8; g4++) {
                int iw3 = 191 - s * 32 - 4 * g4;     // top of descending 4-group
                u64f x3 = valid ? yt[(size_t)(iw3 - 0) * NC + cn] : 0ULL;
                u64f x2 = valid ? yt[(size_t)(iw3 - 1) * NC + cn] : 0ULL;
                u64f x1 = valid ? yt[(size_t)(iw3 - 2) * NC + cn] : 0ULL;
                u64f x0 = valid ? yt[(size_t)(iw3 - 3) * NC + cn] : 0ULL;
                pstep(x3, z, cb, cna);
                pstep(x2, z, cb, cna);
                pstep(x1, z, cb, cna);
                pstep(x0, z, cb, cna);
            }
        }
    }

    // ---- own chunk: iw = 255 down to 0, emit, stage to physical layout ----
    #pragma unroll 1
    for (int g = 0; g < 8; g++) {
        int iwb = 224 - 32 * g;          // base of this 32-sample group
        #pragma unroll
        for (int g4 = 0; g4 < 8; g4++) {
            int iw3 = iwb + 31 - 4 * g4; // descending within group
            u64f x3 = yt[(size_t)(iw3 - 0) * NC + c];
            u64f x2 = yt[(size_t)(iw3 - 1) * NC + c];
            u64f x1 = yt[(size_t)(iw3 - 2) * NC + c];
            u64f x0 = yt[(size_t)(iw3 - 3) * NC + c];
            float2 y3 = upk(pstep(x3, z, cb, cna));   // iw3
            float2 y2 = upk(pstep(x2, z, cb, cna));   // iw3-1
            float2 y1v = upk(pstep(x1, z, cb, cna));  // iw3-2
            float2 y0 = upk(pstep(x0, z, cb, cna));   // iw3-3
            int jl = 7 - g4;             // ascending float4 slot within group
            b0[t * 9 + jl] = make_float4(y0.x, y1v.x, y2.x, y3.x);
            b1[t * 9 + jl] = make_float4(y0.y, y1v.y, y2.y, y3.y);
        }
        __syncthreads();
        #pragma unroll
        for (int l = 0; l < 8; l++) {
            int q = l * NTH + t;
            int tt = q >> 3, j = q & 7;
            int cc = h * NTH + tt;
            int base = cc * CL + iwb + 4 * j;
            *reinterpret_cast<float4*>(o0 + base) = b0[tt * 9 + j];
            *reinterpret_cast<float4*>(o1 + base) = b1[tt * 9 + j];
        }
        __syncthreads();
    }
}

extern "C" void kernel_launch(void* const* d_in, const int* in_sizes, int n_in,
                              void* d_out, int out_size) {
    const float* x = (const float*)d_in[0];
    const float* b = (const float*)d_in[1];
    const float* a = (const float*)d_in[2];
    float* out = (float*)d_out;

    static bool attr_done = false;
    if (!attr_done) {
        cudaFuncSetAttribute(fwd_k, cudaFuncAttributeMaxDynamicSharedMemorySize, SMEM_STG);
        cudaFuncSetAttribute(bwd_k, cudaFuncAttributeMaxDynamicSharedMemorySize, SMEM_STG);
        attr_done = true;
    }

    setup_kernel<<<1, 32>>>(b, a);
    fwd_k<<<GRID, NTH, SMEM_STG>>>(x);
    bwd_k<<<GRID, NTH, SMEM_STG>>>(out);
}

// round 9
// speedup vs baseline: 1.4108x; 1.0621x over previous
#include <cuda_runtime.h>

// Problem constants
#define BB   512
#define TT   65536
#define CL   256                  // chunk length (samples per thread)
#define NC   (TT / CL)            // 256 chunks per row
#define WUS  5                    // warm-up stages (5*32 = 160 samples, decay ~2.6e-6)
#define NTH  128                  // threads per block = half a row pair's chunks
#define NRP  (BB / 2)             // 256 row pairs
#define GRID (NRP * 2)            // 512 blocks

#define BUF_F4   (NTH * 9)
#define SMEM_STG (2 * BUF_F4 * 16)    // 36864 bytes

typedef unsigned long long u64f;

// Intermediate: y1 transposed-packed: yt[iw * NC + c], iw = index within chunk,
// c = chunk index; value packs the two rows of the pair (lo=row0, hi=row1).
__device__ __align__(16) u64f g_y1t[(size_t)NRP * TT];   // 128 MB

// ---------------------------------------------------------------------------
#define FFMA2(d, a, b, c) asm("fma.rn.f32x2 %0, %1, %2, %3;" : "=l"(d) : "l"(a), "l"(b), "l"(c))

__device__ __forceinline__ u64f pk2(float lo, float hi) {
    u64f r; asm("mov.b64 %0, {%1, %2};" : "=l"(r) : "f"(lo), "f"(hi)); return r;
}
__device__ __forceinline__ float2 upk(u64f v) {
    float2 r; asm("mov.b64 {%0, %1}, %2;" : "=f"(r.x), "=f"(r.y) : "l"(v)); return r;
}

__device__ __forceinline__ u64f pstep(u64f x, u64f* z, const u64f* cb, const u64f* cna) {
    u64f y, t;
    FFMA2(y, cb[0], x, z[0]);
    #pragma unroll
    for (int i = 0; i < 7; i++) {
        FFMA2(t, cb[i + 1], x, z[i + 1]);
        FFMA2(z[i], cna[i], y, t);
    }
    u64f zz = 0ULL;
    FFMA2(t, cb[8], x, zz);
    FFMA2(z[7], cna[7], y, t);
    return y;
}

// Inline coefficient computation (replaces the setup kernel; broadcast __ldg)
__device__ __forceinline__ void load_coef_inline(const float* __restrict__ bp,
                                                 const float* __restrict__ ap,
                                                 u64f* cb, u64f* cna) {
    float inv = 1.0f / __ldg(&ap[0]);
    #pragma unroll
    for (int i = 0; i < 9; i++) {
        float bn = __ldg(&bp[i]) * inv;
        cb[i] = pk2(bn, bn);
    }
    #pragma unroll
    for (int i = 1; i < 9; i++) {
        float an = -(__ldg(&ap[i]) * inv);
        cna[i - 1] = pk2(an, an);
    }
}

// ---------------------------------------------------------------------------
// fwd: thread owns chunk c. Zero-state warm-up over the 160 preceding samples,
// then filters its 256-sample chunk, writing y1T inline (coalesced STG.64).
// x staged per 32-sample stage through smem.
// ---------------------------------------------------------------------------
__global__ void __launch_bounds__(NTH) fwd_k(const float* __restrict__ x,
                                             const float* __restrict__ bp,
                                             const float* __restrict__ ap) {
    extern __shared__ char smc[];
    float4* b0 = (float4*)smc;
    float4* b1 = b0 + BUF_F4;

    int rp = blockIdx.x >> 1, h = blockIdx.x & 1, t = threadIdx.x;
    int c = h * NTH + t;                 // chunk 0..255
    const float* p0 = x + (size_t)(rp * 2) * TT;
    const float* p1 = p0 + TT;
    u64f* yt = g_y1t + (size_t)rp * TT;

    u64f cb[9], cna[8];
    load_coef_inline(bp, ap, cb, cna);

    u64f z[8];
    #pragma unroll
    for (int i2 = 0; i2 < 8; i2++) z[i2] = 0ULL;

    #pragma unroll 1
    for (int k = 0; k < 8 + WUS; k++) {
        // slot tt holds 32-sample stage (h*NTH+tt)*8 + k - WUS of this row
        #pragma unroll
        for (int l = 0; l < 8; l++) {
            int q = l * NTH + t;
            int tt = q >> 3, j = q & 7;
            int sg = (h * NTH + tt) * 8 + (k - WUS);
            float4 va = make_float4(0.f, 0.f, 0.f, 0.f);
            float4 vb = va;
            if (sg >= 0) {
                int base = sg * 32 + 4 * j;
                va = *reinterpret_cast<const float4*>(p0 + base);
                vb = *reinterpret_cast<const float4*>(p1 + base);
            }
            b0[tt * 9 + j] = va;
            b1[tt * 9 + j] = vb;
        }
        __syncthreads();
        if (k < WUS) {
            #pragma unroll
            for (int j2 = 0; j2 < 8; j2++) {
                float4 a4 = b0[t * 9 + j2];
                float4 c4 = b1[t * 9 + j2];
                pstep(pk2(a4.x, c4.x), z, cb, cna);
                pstep(pk2(a4.y, c4.y), z, cb, cna);
                pstep(pk2(a4.z, c4.z), z, cb, cna);
                pstep(pk2(a4.w, c4.w), z, cb, cna);
            }
        } else {
            #pragma unroll
            for (int j2 = 0; j2 < 8; j2++) {
                float4 a4 = b0[t * 9 + j2];
                float4 c4 = b1[t * 9 + j2];
                u64f yp0 = pstep(pk2(a4.x, c4.x), z, cb, cna);
                u64f yp1 = pstep(pk2(a4.y, c4.y), z, cb, cna);
                u64f yp2 = pstep(pk2(a4.z, c4.z), z, cb, cna);
                u64f yp3 = pstep(pk2(a4.w, c4.w), z, cb, cna);
                int iw = (k - WUS) * 32 + 4 * j2;    // within-chunk index
                yt[(size_t)(iw + 0) * NC + c] = yp0;
                yt[(size_t)(iw + 1) * NC + c] = yp1;
                yt[(size_t)(iw + 2) * NC + c] = yp2;
                yt[(size_t)(iw + 3) * NC + c] = yp3;
            }
        }
        __syncthreads();
    }
}

// ---------------------------------------------------------------------------
// bwd: thread owns original chunk c; runs the time-reversed filter. Warm-up
// over the 160 samples after the chunk (chunk c+1; zeros past row end = exact
// zero initial state). Rolling prefetch: next 4-sample pack's LDG.64s issue
// before compute on the current pack, decoupling memory latency from the
// serial pstep chain. Output staged to physical layout via smem.
// ---------------------------------------------------------------------------
__global__ void __launch_bounds__(NTH) bwd_k(float* __restrict__ out,
                                             const float* __restrict__ bp,
                                             const float* __restrict__ ap) {
    extern __shared__ char smc[];
    float4* b0 = (float4*)smc;
    float4* b1 = b0 + BUF_F4;

    int rp = blockIdx.x >> 1, h = blockIdx.x & 1, t = threadIdx.x;
    int c = h * NTH + t;                 // original chunk
    const u64f* yt = g_y1t + (size_t)rp * TT;
    float* o0 = out + (size_t)(rp * 2) * TT;
    float* o1 = o0 + TT;

    u64f cb[9], cna[8];
    load_coef_inline(bp, ap, cb, cna);

    u64f z[8];
    #pragma unroll
    for (int i2 = 0; i2 < 8; i2++) z[i2] = 0ULL;

    // ---- warm-up: chunk c+1 samples, iw = 159 down to 0, with prefetch ----
    {
        bool valid = (c + 1 < NC);
        int cn = valid ? (c + 1) : c;    // safe address; value zeroed when !valid
        const u64f* base = yt + cn;
        u64f nx0, nx1, nx2, nx3;
        // preload pack at iw3 = 159
        nx3 = valid ? base[(size_t)159 * NC] : 0ULL;
        nx2 = valid ? base[(size_t)158 * NC] : 0ULL;
        nx1 = valid ? base[(size_t)157 * NC] : 0ULL;
        nx0 = valid ? base[(size_t)156 * NC] : 0ULL;
        #pragma unroll 1
        for (int p = 0; p < WUS * 8; p++) {
            u64f x3 = nx3, x2 = nx2, x1 = nx1, x0 = nx0;
            int niw3 = 159 - 4 * (p + 1);
            if (p + 1 < WUS * 8) {
                nx3 = valid ? base[(size_t)(niw3 - 0) * NC] : 0ULL;
                nx2 = valid ? base[(size_t)(niw3 - 1) * NC] : 0ULL;
                nx1 = valid ? base[(size_t)(niw3 - 2) * NC] : 0ULL;
                nx0 = valid ? base[(size_t)(niw3 - 3) * NC] : 0ULL;
            }
            pstep(x3, z, cb, cna);
            pstep(x2, z, cb, cna);
            pstep(x1, z, cb, cna);
            pstep(x0, z, cb, cna);
        }
    }

    // ---- own chunk: iw = 255 down to 0, rolling prefetch, stage output ----
    {
        const u64f* base = yt + c;
        u64f nx0, nx1, nx2, nx3;
        nx3 = base[(size_t)255 * NC];
        nx2 = base[(size_t)254 * NC];
        nx1 = base[(size_t)253 * NC];
        nx0 = base[(size_t)252 * NC];
        #pragma unroll 1
        for (int g = 0; g < 8; g++) {
            int iwb = 224 - 32 * g;          // base of this 32-sample group
            #pragma unroll
            for (int g4 = 0; g4 < 8; g4++) {
                u64f x3 = nx3, x2 = nx2, x1 = nx1, x0 = nx0;
                int iw3 = iwb + 31 - 4 * g4;
                int niw3 = iw3 - 4;              // next pack top (linear descent)
                if (niw3 >= 3) {
                    nx3 = base[(size_t)(niw3 - 0) * NC];
                    nx2 = base[(size_t)(niw3 - 1) * NC];
                    nx1 = base[(size_t)(niw3 - 2) * NC];
                    nx0 = base[(size_t)(niw3 - 3) * NC];
                }
                float2 y3 = upk(pstep(x3, z, cb, cna));   // iw3
                float2 y2 = upk(pstep(x2, z, cb, cna));   // iw3-1
                float2 y1v = upk(pstep(x1, z, cb, cna));  // iw3-2
                float2 y0 = upk(pstep(x0, z, cb, cna));   // iw3-3
                int jl = 7 - g4;             // ascending float4 slot within group
                b0[t * 9 + jl] = make_float4(y0.x, y1v.x, y2.x, y3.x);
                b1[t * 9 + jl] = make_float4(y0.y, y1v.y, y2.y, y3.y);
            }
            __syncthreads();
            #pragma unroll
            for (int l = 0; l < 8; l++) {
                int q = l * NTH + t;
                int tt = q >> 3, j = q & 7;
                int cc = h * NTH + tt;
                int base2 = cc * CL + iwb + 4 * j;
                *reinterpret_cast<float4*>(o0 + base2) = b0[tt * 9 + j];
                *reinterpret_cast<float4*>(o1 + base2) = b1[tt * 9 + j];
            }
            __syncthreads();
        }
    }
}

extern "C" void kernel_launch(void* const* d_in, const int* in_sizes, int n_in,
                              void* d_out, int out_size) {
    const float* x = (const float*)d_in[0];
    const float* b = (const float*)d_in[1];
    const float* a = (const float*)d_in[2];
    float* out = (float*)d_out;

    static bool attr_done = false;
    if (!attr_done) {
        cudaFuncSetAttribute(fwd_k, cudaFuncAttributeMaxDynamicSharedMemorySize, SMEM_STG);
        cudaFuncSetAttribute(bwd_k, cudaFuncAttributeMaxDynamicSharedMemorySize, SMEM_STG);
        attr_done = true;
    }

    fwd_k<<<GRID, NTH, SMEM_STG>>>(x, b, a);
    bwd_k<<<GRID, NTH, SMEM_STG>>>(out, b, a);
}